// round 5
// baseline (speedup 1.0000x reference)
#include <cuda_runtime.h>

// YOLOv1 loss — smem-staged, class-diff fused into staging pass.
// pred, target: float32 [batch*7*7*30]; out: 5 float32.

static constexpr int CH          = 30;
static constexpr int CELLS_PB    = 49;
static constexpr int NT          = 256;              // threads per block
static constexpr int CELLS_CHUNK = 256;              // cells per chunk (== NT)
static constexpr int F2_CHUNK    = CELLS_CHUNK * CH / 2;  // 3840 float2 per stream
// smem: head pred (256*5 f2) + head tgt (256*5 f2) + class partials (256*10 f)
static constexpr int SH_P_F2     = CELLS_CHUNK * 5;       // 1280 float2
static constexpr int SH_T_F2     = CELLS_CHUNK * 5;       // 1280 float2
static constexpr int SH_CLS_F    = CELLS_CHUNK * 10;      // 2560 float
static constexpr int SMEM_BYTES  = (SH_P_F2 + SH_T_F2) * 8 + SH_CLS_F * 4;  // 30720
static constexpr int MAXBLOCKS   = 4096;

__device__ float        g_part[MAXBLOCKS][4];
__device__ unsigned int g_count = 0;

__device__ __forceinline__ float warp_sum(float v) {
#pragma unroll
    for (int o = 16; o > 0; o >>= 1) v += __shfl_down_sync(0xffffffffu, v, o);
    return v;
}
__device__ __forceinline__ double warp_sum_d(double v) {
#pragma unroll
    for (int o = 16; o > 0; o >>= 1) v += __shfl_down_sync(0xffffffffu, v, o);
    return v;
}

__device__ __forceinline__ float iou_f(float x1, float y1, float w1, float h1,
                                       float x2, float y2, float w2, float h2) {
    float area1 = w1 * h1;
    float area2 = w2 * h2;
    float ml = fmaxf(x1 - w1 * 0.5f, x2 - w2 * 0.5f);
    float mr = fminf(x1 + w1 * 0.5f, x2 + w2 * 0.5f);
    float mt = fmaxf(y1 - h1 * 0.5f, y2 - h2 * 0.5f);
    float mb = fminf(y1 + h1 * 0.5f, y2 + h2 * 0.5f);
    float iw = fmaxf(mr - ml, 0.0f);
    float ih = fmaxf(mb - mt, 0.0f);
    float inter = iw * ih;
    float uni   = area1 + area2 - inter;
    return (inter > 0.0f) ? (inter / uni) : 0.0f;
}

__global__ void __launch_bounds__(NT)
yolo_staged2_kernel(const float* __restrict__ pred,
                    const float* __restrict__ target,
                    int ncells, int nchunks, float inv_bs,
                    float* __restrict__ out) {
    extern __shared__ char smem_raw[];
    float2* sh_p   = reinterpret_cast<float2*>(smem_raw);                 // [SH_P_F2]
    float2* sh_t   = sh_p + SH_P_F2;                                      // [SH_T_F2]
    float*  sh_cls = reinterpret_cast<float*>(sh_t + SH_T_F2);            // [SH_CLS_F]

    const int tid = threadIdx.x;

    float s_coord = 0.0f, s_obj = 0.0f, s_noobj = 0.0f, s_class = 0.0f;

    for (int chunk = blockIdx.x; chunk < nchunks; chunk += gridDim.x) {
        const int cell0 = chunk * CELLS_CHUNK;
        const float2* pg = reinterpret_cast<const float2*>(pred)   + (size_t)cell0 * (CH / 2);
        const float2* tg = reinterpret_cast<const float2*>(target) + (size_t)cell0 * (CH / 2);

        const bool full = (cell0 + CELLS_CHUNK) <= ncells;

        if (full) {
#pragma unroll
            for (int k = 0; k < 15; k++) {
                int idx  = k * NT + tid;            // 0..3839 float2 within chunk
                float2 p = __ldg(pg + idx);
                float2 t = __ldg(tg + idx);
                int cell = idx / 15;
                int j    = idx - cell * 15;         // float2 index within cell
                if (j < 5) {
                    sh_p[cell * 5 + j] = p;
                    sh_t[cell * 5 + j] = t;
                } else {
                    float d0 = p.x - t.x;
                    float d1 = p.y - t.y;
                    sh_cls[cell * 10 + (j - 5)] = d0 * d0 + d1 * d1;
                }
            }
        } else {
            int rem_f2 = (ncells - cell0) * (CH / 2);
            for (int idx = tid; idx < rem_f2; idx += NT) {
                float2 p = __ldg(pg + idx);
                float2 t = __ldg(tg + idx);
                int cell = idx / 15;
                int j    = idx - cell * 15;
                if (j < 5) {
                    sh_p[cell * 5 + j] = p;
                    sh_t[cell * 5 + j] = t;
                } else {
                    float d0 = p.x - t.x;
                    float d1 = p.y - t.y;
                    sh_cls[cell * 10 + (j - 5)] = d0 * d0 + d1 * d1;
                }
            }
        }
        __syncthreads();

        int cell = cell0 + tid;
        if (cell < ncells) {
            float pr[10], tg_h[10];
#pragma unroll
            for (int i = 0; i < 5; i++) {
                float2 v = sh_p[tid * 5 + i];
                pr[2 * i] = v.x; pr[2 * i + 1] = v.y;
                float2 w = sh_t[tid * 5 + i];
                tg_h[2 * i] = w.x; tg_h[2 * i + 1] = w.y;
            }
            float cls = 0.0f;
#pragma unroll
            for (int i = 0; i < 10; i++) cls += sh_cls[tid * 10 + i];

            float obj_f = (tg_h[0] == 1.0f) ? 1.0f : 0.0f;

            float iou1 = iou_f(pr[1], pr[2], pr[3], pr[4],
                               tg_h[1], tg_h[2], tg_h[3], tg_h[4]);
            float iou2 = iou_f(tg_h[6], tg_h[7], tg_h[8], tg_h[9],
                               tg_h[1], tg_h[2], tg_h[3], tg_h[4]);
            bool r = iou1 > iou2;

            float px = r ? pr[1] : pr[6], py = r ? pr[2] : pr[7];
            float tx = r ? tg_h[1] : tg_h[6], ty = r ? tg_h[2] : tg_h[7];
            float pw = r ? pr[3] : pr[8], ph = r ? pr[4] : pr[9];
            float tw = r ? tg_h[3] : tg_h[8], th = r ? tg_h[4] : tg_h[9];

            float dx = px - tx, dy = py - ty;
            float cell_xy = dx * dx + dy * dy;
            float dw = sqrtf(pw) - sqrtf(tw);
            float dh = sqrtf(ph) - sqrtf(th);
            float cell_wh = dw * dw + dh * dh;

            float conf_resp  = r ? pr[0] : pr[5];
            float iou_resp   = r ? iou1  : iou2;
            float d_obj      = conf_resp - iou_resp;

            float conf_other = r ? pr[5] : pr[0];
            float noobj = obj_f * (conf_other * conf_other)
                        + (1.0f - obj_f) * (pr[0] * pr[0] + pr[5] * pr[5]);

            s_coord += obj_f * (cell_xy + cell_wh);
            s_obj   += obj_f * (d_obj * d_obj);
            s_noobj += noobj;
            s_class += obj_f * cls;
        }
        __syncthreads();   // smem reused next chunk
    }

    // ---- intra-block reduction ----
    s_coord = warp_sum(s_coord);
    s_obj   = warp_sum(s_obj);
    s_noobj = warp_sum(s_noobj);
    s_class = warp_sum(s_class);

    __shared__ float sm[NT / 32][4];
    int lane = threadIdx.x & 31;
    int w    = threadIdx.x >> 5;
    if (lane == 0) {
        sm[w][0] = s_coord; sm[w][1] = s_obj;
        sm[w][2] = s_noobj; sm[w][3] = s_class;
    }
    __syncthreads();

    __shared__ bool is_last;
    if (threadIdx.x == 0) is_last = false;

    if (w == 0) {
        float a = (lane < NT / 32) ? sm[lane][0] : 0.0f;
        float b = (lane < NT / 32) ? sm[lane][1] : 0.0f;
        float c = (lane < NT / 32) ? sm[lane][2] : 0.0f;
        float d = (lane < NT / 32) ? sm[lane][3] : 0.0f;
        a = warp_sum(a); b = warp_sum(b); c = warp_sum(c); d = warp_sum(d);
        if (lane == 0) {
            g_part[blockIdx.x][0] = a;
            g_part[blockIdx.x][1] = b;
            g_part[blockIdx.x][2] = c;
            g_part[blockIdx.x][3] = d;
            __threadfence();
            unsigned int ticket = atomicAdd(&g_count, 1u);
            is_last = (ticket == gridDim.x - 1);
        }
    }
    __syncthreads();

    // ---- last block folds partials (fp64, fixed order -> deterministic) ----
    if (is_last) {
        const volatile float* gp = &g_part[0][0];
        double v0 = 0.0, v1 = 0.0, v2 = 0.0, v3 = 0.0;
        for (int i = threadIdx.x; i < (int)gridDim.x; i += NT) {
            v0 += (double)gp[4 * i + 0];
            v1 += (double)gp[4 * i + 1];
            v2 += (double)gp[4 * i + 2];
            v3 += (double)gp[4 * i + 3];
        }
        v0 = warp_sum_d(v0); v1 = warp_sum_d(v1);
        v2 = warp_sum_d(v2); v3 = warp_sum_d(v3);

        __shared__ double smd[NT / 32][4];
        if (lane == 0) { smd[w][0] = v0; smd[w][1] = v1; smd[w][2] = v2; smd[w][3] = v3; }
        __syncthreads();
        if (w == 0) {
            double a = (lane < NT / 32) ? smd[lane][0] : 0.0;
            double b = (lane < NT / 32) ? smd[lane][1] : 0.0;
            double c = (lane < NT / 32) ? smd[lane][2] : 0.0;
            double d = (lane < NT / 32) ? smd[lane][3] : 0.0;
            a = warp_sum_d(a); b = warp_sum_d(b);
            c = warp_sum_d(c); d = warp_sum_d(d);
            if (lane == 0) {
                double coord = 5.0 * a;   // LAMBDA_COORD
                double objl  = b;
                double noobj = 0.5 * c;   // LAMBDA_NOOBJ
                double cls   = d;
                out[0] = (float)(coord * (double)inv_bs);
                out[1] = (float)(objl  * (double)inv_bs);
                out[2] = (float)(noobj * (double)inv_bs);
                out[3] = (float)(cls   * (double)inv_bs);
                out[4] = (float)((coord + objl + noobj + cls) * (double)inv_bs);
                g_count = 0;              // reset for next graph replay
            }
        }
    }
}

extern "C" void kernel_launch(void* const* d_in, const int* in_sizes, int n_in,
                              void* d_out, int out_size) {
    const float* pred   = (const float*)d_in[0];
    const float* target = (const float*)d_in[1];
    float* out = (float*)d_out;

    int total   = in_sizes[0];                       // batch * 49 * 30
    int ncells  = total / CH;                        // batch * 49
    int batch   = ncells / CELLS_PB;
    int nchunks = (ncells + CELLS_CHUNK - 1) / CELLS_CHUNK;   // 3136 for batch=16384
    int nblocks = (nchunks + 2) / 3;                 // each block: exactly ~3 chunks
    if (nblocks > MAXBLOCKS) nblocks = MAXBLOCKS;
    float inv_bs = 1.0f / (float)batch;

    cudaFuncSetAttribute(yolo_staged2_kernel,
                         cudaFuncAttributeMaxDynamicSharedMemorySize, SMEM_BYTES);
    yolo_staged2_kernel<<<nblocks, NT, SMEM_BYTES>>>(pred, target, ncells, nchunks,
                                                     inv_bs, out);
}

// round 6
// speedup vs baseline: 1.1269x; 1.1269x over previous
#include <cuda_runtime.h>

// YOLOv1 loss — warp-autonomous smem staging, no block barriers in main loop.
// pred, target: float32 [batch*7*7*30]; out: 5 float32.

static constexpr int CH        = 30;
static constexpr int CELLS_PB  = 49;
static constexpr int NT        = 128;             // 4 warps per block
static constexpr int NWARPS    = NT / 32;
static constexpr int CELLS_W   = 32;              // cells per warp-chunk
static constexpr int F2_W      = CELLS_W * CH / 2;  // 480 float2 per stream per warp
static constexpr int SMEM_BYTES = NWARPS * 2 * F2_W * 8;   // 30720 B
static constexpr int MAXBLOCKS = 4096;
static constexpr int TARGET_BLOCKS = 1064;        // 152 SMs * 7 blocks

__device__ float        g_part[MAXBLOCKS][4];
__device__ unsigned int g_count = 0;

__device__ __forceinline__ float warp_sum(float v) {
#pragma unroll
    for (int o = 16; o > 0; o >>= 1) v += __shfl_down_sync(0xffffffffu, v, o);
    return v;
}
__device__ __forceinline__ double warp_sum_d(double v) {
#pragma unroll
    for (int o = 16; o > 0; o >>= 1) v += __shfl_down_sync(0xffffffffu, v, o);
    return v;
}

__device__ __forceinline__ float iou_f(float x1, float y1, float w1, float h1,
                                       float x2, float y2, float w2, float h2) {
    float area1 = w1 * h1;
    float area2 = w2 * h2;
    float ml = fmaxf(x1 - w1 * 0.5f, x2 - w2 * 0.5f);
    float mr = fminf(x1 + w1 * 0.5f, x2 + w2 * 0.5f);
    float mt = fmaxf(y1 - h1 * 0.5f, y2 - h2 * 0.5f);
    float mb = fminf(y1 + h1 * 0.5f, y2 + h2 * 0.5f);
    float iw = fmaxf(mr - ml, 0.0f);
    float ih = fmaxf(mb - mt, 0.0f);
    float inter = iw * ih;
    float uni   = area1 + area2 - inter;
    return (inter > 0.0f) ? (inter / uni) : 0.0f;
}

__global__ void __launch_bounds__(NT)
yolo_warp_kernel(const float* __restrict__ pred,
                 const float* __restrict__ target,
                 int ncells, int nchunks, float inv_bs,
                 float* __restrict__ out) {
    extern __shared__ float2 smem[];   // per-warp slices: [wid*960 .. +480) pred, [+480..+960) tgt
    const int lane = threadIdx.x & 31;
    const int wid  = threadIdx.x >> 5;

    float2* sp = smem + (size_t)wid * (2 * F2_W);        // 480 float2
    float2* st = sp + F2_W;                              // 480 float2

    const int gw          = blockIdx.x * NWARPS + wid;   // global warp id
    const int total_warps = gridDim.x * NWARPS;

    float s_coord = 0.0f, s_obj = 0.0f, s_noobj = 0.0f, s_class = 0.0f;

    for (int chunk = gw; chunk < nchunks; chunk += total_warps) {
        const int cell0 = chunk * CELLS_W;
        const float2* pg = reinterpret_cast<const float2*>(pred)   + (size_t)cell0 * (CH / 2);
        const float2* tg = reinterpret_cast<const float2*>(target) + (size_t)cell0 * (CH / 2);

        const bool full = (cell0 + CELLS_W) <= ncells;
        if (full) {
            // 15 coalesced LDG.64 per lane per stream (warp covers 256B/instr).
#pragma unroll
            for (int k = 0; k < 15; k++)
                sp[k * 32 + lane] = __ldcs(pg + k * 32 + lane);
#pragma unroll
            for (int k = 0; k < 15; k++)
                st[k * 32 + lane] = __ldcs(tg + k * 32 + lane);
        } else {
            int rem_f2 = (ncells - cell0) * (CH / 2);
            for (int idx = lane; idx < rem_f2; idx += 32) {
                sp[idx] = __ldcs(pg + idx);
                st[idx] = __ldcs(tg + idx);
            }
        }
        __syncwarp();

        int cell = cell0 + lane;
        if (cell < ncells) {
            const float2* cp = sp + lane * 15;
            const float2* ct = st + lane * 15;

            float pr[10], tg_h[10];
#pragma unroll
            for (int i = 0; i < 5; i++) {
                float2 v = cp[i];
                pr[2 * i] = v.x; pr[2 * i + 1] = v.y;
                float2 w = ct[i];
                tg_h[2 * i] = w.x; tg_h[2 * i + 1] = w.y;
            }
            float cls = 0.0f;
#pragma unroll
            for (int i = 5; i < 15; i++) {
                float2 v = cp[i];
                float2 w = ct[i];
                float d0 = v.x - w.x;
                float d1 = v.y - w.y;
                cls += d0 * d0 + d1 * d1;
            }

            float obj_f = (tg_h[0] == 1.0f) ? 1.0f : 0.0f;

            float iou1 = iou_f(pr[1], pr[2], pr[3], pr[4],
                               tg_h[1], tg_h[2], tg_h[3], tg_h[4]);
            float iou2 = iou_f(tg_h[6], tg_h[7], tg_h[8], tg_h[9],
                               tg_h[1], tg_h[2], tg_h[3], tg_h[4]);
            bool r = iou1 > iou2;

            float px = r ? pr[1] : pr[6], py = r ? pr[2] : pr[7];
            float tx = r ? tg_h[1] : tg_h[6], ty = r ? tg_h[2] : tg_h[7];
            float pw = r ? pr[3] : pr[8], ph = r ? pr[4] : pr[9];
            float tw = r ? tg_h[3] : tg_h[8], th = r ? tg_h[4] : tg_h[9];

            float dx = px - tx, dy = py - ty;
            float cell_xy = dx * dx + dy * dy;
            float dw = sqrtf(pw) - sqrtf(tw);
            float dh = sqrtf(ph) - sqrtf(th);
            float cell_wh = dw * dw + dh * dh;

            float conf_resp  = r ? pr[0] : pr[5];
            float iou_resp   = r ? iou1  : iou2;
            float d_obj      = conf_resp - iou_resp;

            float conf_other = r ? pr[5] : pr[0];
            float noobj = obj_f * (conf_other * conf_other)
                        + (1.0f - obj_f) * (pr[0] * pr[0] + pr[5] * pr[5]);

            s_coord += obj_f * (cell_xy + cell_wh);
            s_obj   += obj_f * (d_obj * d_obj);
            s_noobj += noobj;
            s_class += obj_f * cls;
        }
        __syncwarp();   // warp-private smem reuse
    }

    // ---- intra-block reduction (first barrier of the kernel) ----
    s_coord = warp_sum(s_coord);
    s_obj   = warp_sum(s_obj);
    s_noobj = warp_sum(s_noobj);
    s_class = warp_sum(s_class);

    __shared__ float sm[NWARPS][4];
    if (lane == 0) {
        sm[wid][0] = s_coord; sm[wid][1] = s_obj;
        sm[wid][2] = s_noobj; sm[wid][3] = s_class;
    }
    __syncthreads();

    __shared__ bool is_last;
    if (threadIdx.x == 0) is_last = false;

    if (wid == 0) {
        float a = (lane < NWARPS) ? sm[lane][0] : 0.0f;
        float b = (lane < NWARPS) ? sm[lane][1] : 0.0f;
        float c = (lane < NWARPS) ? sm[lane][2] : 0.0f;
        float d = (lane < NWARPS) ? sm[lane][3] : 0.0f;
        a = warp_sum(a); b = warp_sum(b); c = warp_sum(c); d = warp_sum(d);
        if (lane == 0) {
            g_part[blockIdx.x][0] = a;
            g_part[blockIdx.x][1] = b;
            g_part[blockIdx.x][2] = c;
            g_part[blockIdx.x][3] = d;
            __threadfence();
            unsigned int ticket = atomicAdd(&g_count, 1u);
            is_last = (ticket == gridDim.x - 1);
        }
    }
    __syncthreads();

    // ---- last block folds partials (fp64, fixed order -> deterministic) ----
    if (is_last) {
        const volatile float* gp = &g_part[0][0];
        double v0 = 0.0, v1 = 0.0, v2 = 0.0, v3 = 0.0;
        for (int i = threadIdx.x; i < (int)gridDim.x; i += NT) {
            v0 += (double)gp[4 * i + 0];
            v1 += (double)gp[4 * i + 1];
            v2 += (double)gp[4 * i + 2];
            v3 += (double)gp[4 * i + 3];
        }
        v0 = warp_sum_d(v0); v1 = warp_sum_d(v1);
        v2 = warp_sum_d(v2); v3 = warp_sum_d(v3);

        __shared__ double smd[NWARPS][4];
        if (lane == 0) { smd[wid][0] = v0; smd[wid][1] = v1; smd[wid][2] = v2; smd[wid][3] = v3; }
        __syncthreads();
        if (wid == 0) {
            double a = (lane < NWARPS) ? smd[lane][0] : 0.0;
            double b = (lane < NWARPS) ? smd[lane][1] : 0.0;
            double c = (lane < NWARPS) ? smd[lane][2] : 0.0;
            double d = (lane < NWARPS) ? smd[lane][3] : 0.0;
            a = warp_sum_d(a); b = warp_sum_d(b);
            c = warp_sum_d(c); d = warp_sum_d(d);
            if (lane == 0) {
                double coord = 5.0 * a;   // LAMBDA_COORD
                double objl  = b;
                double noobj = 0.5 * c;   // LAMBDA_NOOBJ
                double cls   = d;
                out[0] = (float)(coord * (double)inv_bs);
                out[1] = (float)(objl  * (double)inv_bs);
                out[2] = (float)(noobj * (double)inv_bs);
                out[3] = (float)(cls   * (double)inv_bs);
                out[4] = (float)((coord + objl + noobj + cls) * (double)inv_bs);
                g_count = 0;              // reset for next graph replay
            }
        }
    }
}

extern "C" void kernel_launch(void* const* d_in, const int* in_sizes, int n_in,
                              void* d_out, int out_size) {
    const float* pred   = (const float*)d_in[0];
    const float* target = (const float*)d_in[1];
    float* out = (float*)d_out;

    int total   = in_sizes[0];                     // batch * 49 * 30
    int ncells  = total / CH;                      // batch * 49
    int batch   = ncells / CELLS_PB;
    int nchunks = (ncells + CELLS_W - 1) / CELLS_W;   // 25088 for batch=16384
    int nblocks = TARGET_BLOCKS;
    int maxb    = (nchunks + NWARPS - 1) / NWARPS;    // at least 1 chunk per block
    if (nblocks > maxb) nblocks = maxb;
    if (nblocks > MAXBLOCKS) nblocks = MAXBLOCKS;
    float inv_bs = 1.0f / (float)batch;

    cudaFuncSetAttribute(yolo_warp_kernel,
                         cudaFuncAttributeMaxDynamicSharedMemorySize, SMEM_BYTES);
    yolo_warp_kernel<<<nblocks, NT, SMEM_BYTES>>>(pred, target, ncells, nchunks,
                                                  inv_bs, out);
}

// round 7
// speedup vs baseline: 1.2291x; 1.0907x over previous
#include <cuda_runtime.h>
#include <cstdint>

// YOLOv1 loss — cp.async double-buffered streaming, one block per SM.
// pred, target: float32 [batch*7*7*30]; out: 5 float32.

static constexpr int CH        = 30;
static constexpr int CELLS_PB  = 49;
static constexpr int NT        = 256;                 // threads per block
static constexpr int CC        = 256;                 // cells per chunk
static constexpr int F4_PRED   = CC * CH / 4;         // 1920 float4 (pred stream)
static constexpr int F4_CHUNK  = 2 * F4_PRED;         // 3840 float4 per chunk (pred+tgt)
static constexpr int BUF_BYTES = F4_CHUNK * 16;       // 61440 B per buffer
static constexpr int SMEM_BYTES = 2 * BUF_BYTES;      // 122880 B
static constexpr int NSMS      = 152;
static constexpr int MAXBLOCKS = 512;

__device__ float        g_part[MAXBLOCKS][4];
__device__ unsigned int g_count = 0;

__device__ __forceinline__ void cp_async16(void* sdst, const void* gsrc) {
    uint32_t s = (uint32_t)__cvta_generic_to_shared(sdst);
    asm volatile("cp.async.cg.shared.global [%0], [%1], 16;" :: "r"(s), "l"(gsrc));
}
__device__ __forceinline__ void cp_async8(void* sdst, const void* gsrc) {
    uint32_t s = (uint32_t)__cvta_generic_to_shared(sdst);
    asm volatile("cp.async.ca.shared.global [%0], [%1], 8;" :: "r"(s), "l"(gsrc));
}
__device__ __forceinline__ void cp_commit() {
    asm volatile("cp.async.commit_group;");
}
template <int N>
__device__ __forceinline__ void cp_wait() {
    asm volatile("cp.async.wait_group %0;" :: "n"(N));
}

__device__ __forceinline__ float warp_sum(float v) {
#pragma unroll
    for (int o = 16; o > 0; o >>= 1) v += __shfl_down_sync(0xffffffffu, v, o);
    return v;
}
__device__ __forceinline__ double warp_sum_d(double v) {
#pragma unroll
    for (int o = 16; o > 0; o >>= 1) v += __shfl_down_sync(0xffffffffu, v, o);
    return v;
}

__device__ __forceinline__ float iou_f(float x1, float y1, float w1, float h1,
                                       float x2, float y2, float w2, float h2) {
    float area1 = w1 * h1;
    float area2 = w2 * h2;
    float ml = fmaxf(x1 - w1 * 0.5f, x2 - w2 * 0.5f);
    float mr = fminf(x1 + w1 * 0.5f, x2 + w2 * 0.5f);
    float mt = fmaxf(y1 - h1 * 0.5f, y2 - h2 * 0.5f);
    float mb = fminf(y1 + h1 * 0.5f, y2 + h2 * 0.5f);
    float iw = fmaxf(mr - ml, 0.0f);
    float ih = fmaxf(mb - mt, 0.0f);
    float inter = iw * ih;
    float uni   = area1 + area2 - inter;
    return (inter > 0.0f) ? (inter / uni) : 0.0f;
}

__global__ void __launch_bounds__(NT)
yolo_pipe_kernel(const float* __restrict__ pred,
                 const float* __restrict__ target,
                 int ncells, int nchunks, float inv_bs,
                 float* __restrict__ out) {
    extern __shared__ float4 sbuf[];   // [2][F4_CHUNK]
    const int tid = threadIdx.x;

    // Contiguous balanced chunk range for this block.
    int nb   = gridDim.x;
    int base = nchunks / nb;
    int rem  = nchunks - base * nb;
    int b    = blockIdx.x;
    int c_begin = b * base + (b < rem ? b : rem);
    int c_end   = c_begin + base + (b < rem ? 1 : 0);

    // ---- stage one chunk (cp.async, no waits) ----
    auto stage = [&](int c, int which) {
        float4* dst = sbuf + (size_t)which * F4_CHUNK;
        const int cell0 = c * CC;
        if (cell0 + CC <= ncells) {
            const float4* pg = reinterpret_cast<const float4*>(pred   + (size_t)cell0 * CH);
            const float4* tg = reinterpret_cast<const float4*>(target + (size_t)cell0 * CH);
#pragma unroll
            for (int k = 0; k < F4_CHUNK / NT; k++) {   // 15 iterations
                int idx = k * NT + tid;
                const float4* src = (idx < F4_PRED) ? (pg + idx) : (tg + (idx - F4_PRED));
                cp_async16(dst + idx, src);
            }
        } else {
            // partial last chunk: guarded 8B copies
            int rem_f2 = (ncells - cell0) * (CH / 2);
            const float2* pg2 = reinterpret_cast<const float2*>(pred   + (size_t)cell0 * CH);
            const float2* tg2 = reinterpret_cast<const float2*>(target + (size_t)cell0 * CH);
            float2* d2p = reinterpret_cast<float2*>(dst);
            float2* d2t = d2p + 2 * F4_PRED;   // tgt region in float2 units
            for (int idx = tid; idx < rem_f2; idx += NT) {
                cp_async8(d2p + idx, pg2 + idx);
                cp_async8(d2t + idx, tg2 + idx);
            }
        }
        cp_commit();
    };

    float s_coord = 0.0f, s_obj = 0.0f, s_noobj = 0.0f, s_class = 0.0f;

    if (c_begin < c_end) stage(c_begin, 0);

    for (int c = c_begin; c < c_end; c++) {
        int which = (c - c_begin) & 1;
        if (c + 1 < c_end) {
            stage(c + 1, which ^ 1);
            cp_wait<1>();     // chunk c's group complete (c+1 still pending)
        } else {
            cp_wait<0>();
        }
        __syncthreads();

        const int cell0 = c * CC;
        const int cell  = cell0 + tid;
        if (cell < ncells) {
            const float2* bp = reinterpret_cast<const float2*>(sbuf + (size_t)which * F4_CHUNK);
            const float2* cp = bp + (size_t)tid * 15;                 // pred cell
            const float2* ct = bp + 2 * F4_PRED + (size_t)tid * 15;   // tgt cell

            float pr[10], tg_h[10];
#pragma unroll
            for (int i = 0; i < 5; i++) {
                float2 v = cp[i];
                pr[2 * i] = v.x; pr[2 * i + 1] = v.y;
                float2 w = ct[i];
                tg_h[2 * i] = w.x; tg_h[2 * i + 1] = w.y;
            }
            float cls = 0.0f;
#pragma unroll
            for (int i = 5; i < 15; i++) {
                float2 v = cp[i];
                float2 w = ct[i];
                float d0 = v.x - w.x;
                float d1 = v.y - w.y;
                cls += d0 * d0 + d1 * d1;
            }

            float obj_f = (tg_h[0] == 1.0f) ? 1.0f : 0.0f;

            float iou1 = iou_f(pr[1], pr[2], pr[3], pr[4],
                               tg_h[1], tg_h[2], tg_h[3], tg_h[4]);
            float iou2 = iou_f(tg_h[6], tg_h[7], tg_h[8], tg_h[9],
                               tg_h[1], tg_h[2], tg_h[3], tg_h[4]);
            bool r = iou1 > iou2;

            float px = r ? pr[1] : pr[6], py = r ? pr[2] : pr[7];
            float tx = r ? tg_h[1] : tg_h[6], ty = r ? tg_h[2] : tg_h[7];
            float pw = r ? pr[3] : pr[8], ph = r ? pr[4] : pr[9];
            float tw = r ? tg_h[3] : tg_h[8], th = r ? tg_h[4] : tg_h[9];

            float dx = px - tx, dy = py - ty;
            float cell_xy = dx * dx + dy * dy;
            float dw = sqrtf(pw) - sqrtf(tw);
            float dh = sqrtf(ph) - sqrtf(th);
            float cell_wh = dw * dw + dh * dh;

            float conf_resp  = r ? pr[0] : pr[5];
            float iou_resp   = r ? iou1  : iou2;
            float d_obj      = conf_resp - iou_resp;

            float conf_other = r ? pr[5] : pr[0];
            float noobj = obj_f * (conf_other * conf_other)
                        + (1.0f - obj_f) * (pr[0] * pr[0] + pr[5] * pr[5]);

            s_coord += obj_f * (cell_xy + cell_wh);
            s_obj   += obj_f * (d_obj * d_obj);
            s_noobj += noobj;
            s_class += obj_f * cls;
        }
        __syncthreads();   // buffer reuse (chunk c+2 overwrites this buffer)
    }

    // ---- intra-block reduction ----
    s_coord = warp_sum(s_coord);
    s_obj   = warp_sum(s_obj);
    s_noobj = warp_sum(s_noobj);
    s_class = warp_sum(s_class);

    __shared__ float sm[NT / 32][4];
    int lane = threadIdx.x & 31;
    int w    = threadIdx.x >> 5;
    if (lane == 0) {
        sm[w][0] = s_coord; sm[w][1] = s_obj;
        sm[w][2] = s_noobj; sm[w][3] = s_class;
    }
    __syncthreads();

    __shared__ bool is_last;
    if (threadIdx.x == 0) is_last = false;

    if (w == 0) {
        float a = (lane < NT / 32) ? sm[lane][0] : 0.0f;
        float bq = (lane < NT / 32) ? sm[lane][1] : 0.0f;
        float cq = (lane < NT / 32) ? sm[lane][2] : 0.0f;
        float dq = (lane < NT / 32) ? sm[lane][3] : 0.0f;
        a = warp_sum(a); bq = warp_sum(bq); cq = warp_sum(cq); dq = warp_sum(dq);
        if (lane == 0) {
            g_part[blockIdx.x][0] = a;
            g_part[blockIdx.x][1] = bq;
            g_part[blockIdx.x][2] = cq;
            g_part[blockIdx.x][3] = dq;
            __threadfence();
            unsigned int ticket = atomicAdd(&g_count, 1u);
            is_last = (ticket == gridDim.x - 1);
        }
    }
    __syncthreads();

    // ---- last block folds partials (fp64, fixed order -> deterministic) ----
    if (is_last) {
        const volatile float* gp = &g_part[0][0];
        double v0 = 0.0, v1 = 0.0, v2 = 0.0, v3 = 0.0;
        for (int i = threadIdx.x; i < (int)gridDim.x; i += NT) {
            v0 += (double)gp[4 * i + 0];
            v1 += (double)gp[4 * i + 1];
            v2 += (double)gp[4 * i + 2];
            v3 += (double)gp[4 * i + 3];
        }
        v0 = warp_sum_d(v0); v1 = warp_sum_d(v1);
        v2 = warp_sum_d(v2); v3 = warp_sum_d(v3);

        __shared__ double smd[NT / 32][4];
        if (lane == 0) { smd[w][0] = v0; smd[w][1] = v1; smd[w][2] = v2; smd[w][3] = v3; }
        __syncthreads();
        if (w == 0) {
            double a = (lane < NT / 32) ? smd[lane][0] : 0.0;
            double bq = (lane < NT / 32) ? smd[lane][1] : 0.0;
            double cq = (lane < NT / 32) ? smd[lane][2] : 0.0;
            double dq = (lane < NT / 32) ? smd[lane][3] : 0.0;
            a = warp_sum_d(a); bq = warp_sum_d(bq);
            cq = warp_sum_d(cq); dq = warp_sum_d(dq);
            if (lane == 0) {
                double coord = 5.0 * a;   // LAMBDA_COORD
                double objl  = bq;
                double noobj = 0.5 * cq;  // LAMBDA_NOOBJ
                double cls   = dq;
                out[0] = (float)(coord * (double)inv_bs);
                out[1] = (float)(objl  * (double)inv_bs);
                out[2] = (float)(noobj * (double)inv_bs);
                out[3] = (float)(cls   * (double)inv_bs);
                out[4] = (float)((coord + objl + noobj + cls) * (double)inv_bs);
                g_count = 0;              // reset for next graph replay
            }
        }
    }
}

extern "C" void kernel_launch(void* const* d_in, const int* in_sizes, int n_in,
                              void* d_out, int out_size) {
    const float* pred   = (const float*)d_in[0];
    const float* target = (const float*)d_in[1];
    float* out = (float*)d_out;

    int total   = in_sizes[0];                   // batch * 49 * 30
    int ncells  = total / CH;                    // batch * 49
    int batch   = ncells / CELLS_PB;
    int nchunks = (ncells + CC - 1) / CC;        // 3136 for batch=16384
    int nblocks = NSMS;                          // one block per SM
    if (nblocks > nchunks) nblocks = nchunks;
    if (nblocks > MAXBLOCKS) nblocks = MAXBLOCKS;
    float inv_bs = 1.0f / (float)batch;

    cudaFuncSetAttribute(yolo_pipe_kernel,
                         cudaFuncAttributeMaxDynamicSharedMemorySize, SMEM_BYTES);
    yolo_pipe_kernel<<<nblocks, NT, SMEM_BYTES>>>(pred, target, ncells, nchunks,
                                                  inv_bs, out);
}

// round 8
// speedup vs baseline: 1.2785x; 1.0402x over previous
#include <cuda_runtime.h>
#include <cstdint>

// YOLOv1 loss — cp.async double-buffered streaming + MUFU-reduced math.
// pred, target: float32 [batch*7*7*30]; out: 5 float32.

static constexpr int CH        = 30;
static constexpr int CELLS_PB  = 49;
static constexpr int NT        = 256;                 // threads per block
static constexpr int CC        = 256;                 // cells per chunk
static constexpr int F4_PRED   = CC * CH / 4;         // 1920 float4 (pred stream)
static constexpr int F4_CHUNK  = 2 * F4_PRED;         // 3840 float4 per chunk
static constexpr int BUF_BYTES = F4_CHUNK * 16;       // 61440 B per buffer
static constexpr int SMEM_BYTES = 2 * BUF_BYTES;      // 122880 B
static constexpr int NSMS      = 152;
static constexpr int MAXBLOCKS = 512;

__device__ float        g_part[MAXBLOCKS][4];
__device__ unsigned int g_count = 0;

__device__ __forceinline__ void cp_async16(void* sdst, const void* gsrc) {
    uint32_t s = (uint32_t)__cvta_generic_to_shared(sdst);
    asm volatile("cp.async.cg.shared.global [%0], [%1], 16;" :: "r"(s), "l"(gsrc));
}
__device__ __forceinline__ void cp_async8(void* sdst, const void* gsrc) {
    uint32_t s = (uint32_t)__cvta_generic_to_shared(sdst);
    asm volatile("cp.async.ca.shared.global [%0], [%1], 8;" :: "r"(s), "l"(gsrc));
}
__device__ __forceinline__ void cp_commit() {
    asm volatile("cp.async.commit_group;");
}
template <int N>
__device__ __forceinline__ void cp_wait() {
    asm volatile("cp.async.wait_group %0;" :: "n"(N));
}

__device__ __forceinline__ float sqrt_approx(float x) {
    float r;
    asm("sqrt.approx.f32 %0, %1;" : "=f"(r) : "f"(x));
    return r;
}

__device__ __forceinline__ float warp_sum(float v) {
#pragma unroll
    for (int o = 16; o > 0; o >>= 1) v += __shfl_down_sync(0xffffffffu, v, o);
    return v;
}
__device__ __forceinline__ double warp_sum_d(double v) {
#pragma unroll
    for (int o = 16; o > 0; o >>= 1) v += __shfl_down_sync(0xffffffffu, v, o);
    return v;
}

// Intersection and union (no division).
__device__ __forceinline__ void inter_union(float x1, float y1, float w1, float h1,
                                            float x2, float y2, float w2, float h2,
                                            float& inter, float& uni) {
    float ml = fmaxf(x1 - w1 * 0.5f, x2 - w2 * 0.5f);
    float mr = fminf(x1 + w1 * 0.5f, x2 + w2 * 0.5f);
    float mt = fmaxf(y1 - h1 * 0.5f, y2 - h2 * 0.5f);
    float mb = fminf(y1 + h1 * 0.5f, y2 + h2 * 0.5f);
    float iw = fmaxf(mr - ml, 0.0f);
    float ih = fmaxf(mb - mt, 0.0f);
    inter = iw * ih;
    uni   = w1 * h1 + w2 * h2 - inter;
}

__global__ void __launch_bounds__(NT)
yolo_pipe2_kernel(const float* __restrict__ pred,
                  const float* __restrict__ target,
                  int ncells, int nchunks, float inv_bs,
                  float* __restrict__ out) {
    extern __shared__ float4 sbuf[];   // [2][F4_CHUNK]
    const int tid = threadIdx.x;

    // Contiguous balanced chunk range for this block.
    int nb   = gridDim.x;
    int base = nchunks / nb;
    int rem  = nchunks - base * nb;
    int b    = blockIdx.x;
    int c_begin = b * base + (b < rem ? b : rem);
    int c_end   = c_begin + base + (b < rem ? 1 : 0);

    auto stage = [&](int c, int which) {
        float4* dst = sbuf + (size_t)which * F4_CHUNK;
        const int cell0 = c * CC;
        if (cell0 + CC <= ncells) {
            const float4* pg = reinterpret_cast<const float4*>(pred   + (size_t)cell0 * CH);
            const float4* tg = reinterpret_cast<const float4*>(target + (size_t)cell0 * CH);
#pragma unroll
            for (int k = 0; k < F4_CHUNK / NT; k++) {   // 15
                int idx = k * NT + tid;
                const float4* src = (idx < F4_PRED) ? (pg + idx) : (tg + (idx - F4_PRED));
                cp_async16(dst + idx, src);
            }
        } else {
            int rem_f2 = (ncells - cell0) * (CH / 2);
            const float2* pg2 = reinterpret_cast<const float2*>(pred   + (size_t)cell0 * CH);
            const float2* tg2 = reinterpret_cast<const float2*>(target + (size_t)cell0 * CH);
            float2* d2p = reinterpret_cast<float2*>(dst);
            float2* d2t = d2p + 2 * F4_PRED;
            for (int idx = tid; idx < rem_f2; idx += NT) {
                cp_async8(d2p + idx, pg2 + idx);
                cp_async8(d2t + idx, tg2 + idx);
            }
        }
        cp_commit();
    };

    float s_coord = 0.0f, s_obj = 0.0f, s_noobj = 0.0f, s_class = 0.0f;

    if (c_begin < c_end) stage(c_begin, 0);

    for (int c = c_begin; c < c_end; c++) {
        int which = (c - c_begin) & 1;
        if (c + 1 < c_end) {
            stage(c + 1, which ^ 1);
            cp_wait<1>();
        } else {
            cp_wait<0>();
        }
        __syncthreads();

        const int cell0 = c * CC;
        const int cell  = cell0 + tid;
        if (cell < ncells) {
            const float2* bp = reinterpret_cast<const float2*>(sbuf + (size_t)which * F4_CHUNK);
            const float2* cp = bp + (size_t)tid * 15;                 // pred cell
            const float2* ct = bp + 2 * F4_PRED + (size_t)tid * 15;   // tgt cell

            float pr[10], tg_h[10];
#pragma unroll
            for (int i = 0; i < 5; i++) {
                float2 v = cp[i];
                pr[2 * i] = v.x; pr[2 * i + 1] = v.y;
                float2 w = ct[i];
                tg_h[2 * i] = w.x; tg_h[2 * i + 1] = w.y;
            }
            float cls = 0.0f;
#pragma unroll
            for (int i = 5; i < 15; i++) {
                float2 v = cp[i];
                float2 w = ct[i];
                float d0 = v.x - w.x;
                float d1 = v.y - w.y;
                cls += d0 * d0 + d1 * d1;
            }

            float obj_f = (tg_h[0] == 1.0f) ? 1.0f : 0.0f;

            // IoU numerators/denominators (no divides).
            float i1, u1, i2, u2;
            inter_union(pr[1], pr[2], pr[3], pr[4],
                        tg_h[1], tg_h[2], tg_h[3], tg_h[4], i1, u1);
            inter_union(tg_h[6], tg_h[7], tg_h[8], tg_h[9],
                        tg_h[1], tg_h[2], tg_h[3], tg_h[4], i2, u2);

            // resp1 = iou1 > iou2  <=>  i1*u2 > i2*u1  (exact; see analysis)
            bool r = (i1 * u2) > (i2 * u1);

            float px = r ? pr[1] : pr[6], py = r ? pr[2] : pr[7];
            float tx = r ? tg_h[1] : tg_h[6], ty = r ? tg_h[2] : tg_h[7];
            float pw = r ? pr[3] : pr[8], ph = r ? pr[4] : pr[9];
            float tw = r ? tg_h[3] : tg_h[8], th = r ? tg_h[4] : tg_h[9];

            float dx = px - tx, dy = py - ty;
            float cell_xy = dx * dx + dy * dy;
            // (sqrt(pw)-sqrt(tw))^2 + (sqrt(ph)-sqrt(th))^2
            //   = pw+tw-2*sqrt(pw*tw) + ph+th-2*sqrt(ph*th)   (2 MUFU instead of 4)
            float cell_wh = pw + tw - 2.0f * sqrt_approx(pw * tw)
                          + ph + th - 2.0f * sqrt_approx(ph * th);

            // Selected IoU: single fast divide.
            float num_r = r ? i1 : i2;
            float den_r = r ? u1 : u2;
            float iou_resp = (num_r > 0.0f) ? __fdividef(num_r, den_r) : 0.0f;

            float conf_resp  = r ? pr[0] : pr[5];
            float d_obj      = conf_resp - iou_resp;

            float conf_other = r ? pr[5] : pr[0];
            float noobj = obj_f * (conf_other * conf_other)
                        + (1.0f - obj_f) * (pr[0] * pr[0] + pr[5] * pr[5]);

            s_coord += obj_f * (cell_xy + cell_wh);
            s_obj   += obj_f * (d_obj * d_obj);
            s_noobj += noobj;
            s_class += obj_f * cls;
        }
        __syncthreads();
    }

    // ---- intra-block reduction ----
    s_coord = warp_sum(s_coord);
    s_obj   = warp_sum(s_obj);
    s_noobj = warp_sum(s_noobj);
    s_class = warp_sum(s_class);

    __shared__ float sm[NT / 32][4];
    int lane = threadIdx.x & 31;
    int w    = threadIdx.x >> 5;
    if (lane == 0) {
        sm[w][0] = s_coord; sm[w][1] = s_obj;
        sm[w][2] = s_noobj; sm[w][3] = s_class;
    }
    __syncthreads();

    __shared__ bool is_last;
    if (threadIdx.x == 0) is_last = false;

    if (w == 0) {
        float a = (lane < NT / 32) ? sm[lane][0] : 0.0f;
        float bq = (lane < NT / 32) ? sm[lane][1] : 0.0f;
        float cq = (lane < NT / 32) ? sm[lane][2] : 0.0f;
        float dq = (lane < NT / 32) ? sm[lane][3] : 0.0f;
        a = warp_sum(a); bq = warp_sum(bq); cq = warp_sum(cq); dq = warp_sum(dq);
        if (lane == 0) {
            g_part[blockIdx.x][0] = a;
            g_part[blockIdx.x][1] = bq;
            g_part[blockIdx.x][2] = cq;
            g_part[blockIdx.x][3] = dq;
            __threadfence();
            unsigned int ticket = atomicAdd(&g_count, 1u);
            is_last = (ticket == gridDim.x - 1);
        }
    }
    __syncthreads();

    if (is_last) {
        const volatile float* gp = &g_part[0][0];
        double v0 = 0.0, v1 = 0.0, v2 = 0.0, v3 = 0.0;
        for (int i = threadIdx.x; i < (int)gridDim.x; i += NT) {
            v0 += (double)gp[4 * i + 0];
            v1 += (double)gp[4 * i + 1];
            v2 += (double)gp[4 * i + 2];
            v3 += (double)gp[4 * i + 3];
        }
        v0 = warp_sum_d(v0); v1 = warp_sum_d(v1);
        v2 = warp_sum_d(v2); v3 = warp_sum_d(v3);

        __shared__ double smd[NT / 32][4];
        if (lane == 0) { smd[w][0] = v0; smd[w][1] = v1; smd[w][2] = v2; smd[w][3] = v3; }
        __syncthreads();
        if (w == 0) {
            double a = (lane < NT / 32) ? smd[lane][0] : 0.0;
            double bq = (lane < NT / 32) ? smd[lane][1] : 0.0;
            double cq = (lane < NT / 32) ? smd[lane][2] : 0.0;
            double dq = (lane < NT / 32) ? smd[lane][3] : 0.0;
            a = warp_sum_d(a); bq = warp_sum_d(bq);
            cq = warp_sum_d(cq); dq = warp_sum_d(dq);
            if (lane == 0) {
                double coord = 5.0 * a;   // LAMBDA_COORD
                double objl  = bq;
                double noobj = 0.5 * cq;  // LAMBDA_NOOBJ
                double cls   = dq;
                out[0] = (float)(coord * (double)inv_bs);
                out[1] = (float)(objl  * (double)inv_bs);
                out[2] = (float)(noobj * (double)inv_bs);
                out[3] = (float)(cls   * (double)inv_bs);
                out[4] = (float)((coord + objl + noobj + cls) * (double)inv_bs);
                g_count = 0;
            }
        }
    }
}

extern "C" void kernel_launch(void* const* d_in, const int* in_sizes, int n_in,
                              void* d_out, int out_size) {
    const float* pred   = (const float*)d_in[0];
    const float* target = (const float*)d_in[1];
    float* out = (float*)d_out;

    int total   = in_sizes[0];                   // batch * 49 * 30
    int ncells  = total / CH;                    // batch * 49
    int batch   = ncells / CELLS_PB;
    int nchunks = (ncells + CC - 1) / CC;        // 3136 for batch=16384
    int nblocks = NSMS;
    if (nblocks > nchunks) nblocks = nchunks;
    if (nblocks > MAXBLOCKS) nblocks = MAXBLOCKS;
    float inv_bs = 1.0f / (float)batch;

    cudaFuncSetAttribute(yolo_pipe2_kernel,
                         cudaFuncAttributeMaxDynamicSharedMemorySize, SMEM_BYTES);
    yolo_pipe2_kernel<<<nblocks, NT, SMEM_BYTES>>>(pred, target, ncells, nchunks,
                                                   inv_bs, out);
}

// round 9
// speedup vs baseline: 1.2860x; 1.0059x over previous
#include <cuda_runtime.h>
#include <cstdint>

// YOLOv1 loss — cp.async double-buffered streaming, 2 threads per cell.
// pred, target: float32 [batch*7*7*30]; out: 5 float32.

static constexpr int CH        = 30;
static constexpr int CELLS_PB  = 49;
static constexpr int NT        = 512;                 // threads per block (2 per cell)
static constexpr int CC        = 256;                 // cells per chunk
static constexpr int F4_PRED   = CC * CH / 4;         // 1920 float4 (pred stream)
static constexpr int F4_CHUNK  = 2 * F4_PRED;         // 3840 float4 per chunk
static constexpr int BUF_BYTES = F4_CHUNK * 16;       // 61440 B per buffer
static constexpr int SMEM_BYTES = 2 * BUF_BYTES;      // 122880 B
static constexpr int NSMS      = 152;
static constexpr int MAXBLOCKS = 512;

__device__ float        g_part[MAXBLOCKS][4];
__device__ unsigned int g_count = 0;

__device__ __forceinline__ void cp_async16(void* sdst, const void* gsrc) {
    uint32_t s = (uint32_t)__cvta_generic_to_shared(sdst);
    asm volatile("cp.async.cg.shared.global [%0], [%1], 16;" :: "r"(s), "l"(gsrc));
}
__device__ __forceinline__ void cp_async8(void* sdst, const void* gsrc) {
    uint32_t s = (uint32_t)__cvta_generic_to_shared(sdst);
    asm volatile("cp.async.ca.shared.global [%0], [%1], 8;" :: "r"(s), "l"(gsrc));
}
__device__ __forceinline__ void cp_commit() {
    asm volatile("cp.async.commit_group;");
}
template <int N>
__device__ __forceinline__ void cp_wait() {
    asm volatile("cp.async.wait_group %0;" :: "n"(N));
}

__device__ __forceinline__ float sqrt_approx(float x) {
    float r;
    asm("sqrt.approx.f32 %0, %1;" : "=f"(r) : "f"(x));
    return r;
}

__device__ __forceinline__ float warp_sum(float v) {
#pragma unroll
    for (int o = 16; o > 0; o >>= 1) v += __shfl_down_sync(0xffffffffu, v, o);
    return v;
}
__device__ __forceinline__ double warp_sum_d(double v) {
#pragma unroll
    for (int o = 16; o > 0; o >>= 1) v += __shfl_down_sync(0xffffffffu, v, o);
    return v;
}

__device__ __forceinline__ void inter_union(float x1, float y1, float w1, float h1,
                                            float x2, float y2, float w2, float h2,
                                            float& inter, float& uni) {
    float ml = fmaxf(x1 - w1 * 0.5f, x2 - w2 * 0.5f);
    float mr = fminf(x1 + w1 * 0.5f, x2 + w2 * 0.5f);
    float mt = fmaxf(y1 - h1 * 0.5f, y2 - h2 * 0.5f);
    float mb = fminf(y1 + h1 * 0.5f, y2 + h2 * 0.5f);
    float iw = fmaxf(mr - ml, 0.0f);
    float ih = fmaxf(mb - mt, 0.0f);
    inter = iw * ih;
    uni   = w1 * h1 + w2 * h2 - inter;
}

__global__ void __launch_bounds__(NT)
yolo_pipe3_kernel(const float* __restrict__ pred,
                  const float* __restrict__ target,
                  int ncells, int nchunks, float inv_bs,
                  float* __restrict__ out) {
    extern __shared__ float4 sbuf[];   // [2][F4_CHUNK]
    const int tid = threadIdx.x;

    // Contiguous balanced chunk range for this block.
    int nb   = gridDim.x;
    int base = nchunks / nb;
    int rem  = nchunks - base * nb;
    int b    = blockIdx.x;
    int c_begin = b * base + (b < rem ? b : rem);
    int c_end   = c_begin + base + (b < rem ? 1 : 0);

    auto stage = [&](int c, int which) {
        float4* dst = sbuf + (size_t)which * F4_CHUNK;
        const int cell0 = c * CC;
        if (cell0 + CC <= ncells) {
            const float4* pg = reinterpret_cast<const float4*>(pred   + (size_t)cell0 * CH);
            const float4* tg = reinterpret_cast<const float4*>(target + (size_t)cell0 * CH);
#pragma unroll
            for (int k = 0; k < (F4_CHUNK + NT - 1) / NT; k++) {   // 8, last guarded
                int idx = k * NT + tid;
                if (idx < F4_CHUNK) {
                    const float4* src = (idx < F4_PRED) ? (pg + idx) : (tg + (idx - F4_PRED));
                    cp_async16(dst + idx, src);
                }
            }
        } else {
            int rem_f2 = (ncells - cell0) * (CH / 2);
            const float2* pg2 = reinterpret_cast<const float2*>(pred   + (size_t)cell0 * CH);
            const float2* tg2 = reinterpret_cast<const float2*>(target + (size_t)cell0 * CH);
            float2* d2p = reinterpret_cast<float2*>(dst);
            float2* d2t = d2p + 2 * F4_PRED;
            for (int idx = tid; idx < rem_f2; idx += NT) {
                cp_async8(d2p + idx, pg2 + idx);
                cp_async8(d2t + idx, tg2 + idx);
            }
        }
        cp_commit();
    };

    float s_coord = 0.0f, s_obj = 0.0f, s_noobj = 0.0f, s_class = 0.0f;

    if (c_begin < c_end) stage(c_begin, 0);

    for (int c = c_begin; c < c_end; c++) {
        int which = (c - c_begin) & 1;
        if (c + 1 < c_end) {
            stage(c + 1, which ^ 1);
            cp_wait<1>();
        } else {
            cp_wait<0>();
        }
        __syncthreads();

        const int cell0 = c * CC;
        const float2* bp = reinterpret_cast<const float2*>(sbuf + (size_t)which * F4_CHUNK);
        const float2* bt = bp + 2 * F4_PRED;   // target region (float2 units)

        if (tid < CC) {
            // ---- HEAD thread: channels 0..9 of cell (cell0 + tid) ----
            const int cell = cell0 + tid;
            if (cell < ncells) {
                const float2* cp = bp + (size_t)tid * 15;
                const float2* ct = bt + (size_t)tid * 15;

                float pr[10], tg_h[10];
#pragma unroll
                for (int i = 0; i < 5; i++) {
                    float2 v = cp[i];
                    pr[2 * i] = v.x; pr[2 * i + 1] = v.y;
                    float2 w = ct[i];
                    tg_h[2 * i] = w.x; tg_h[2 * i + 1] = w.y;
                }

                float obj_f = (tg_h[0] == 1.0f) ? 1.0f : 0.0f;

                float i1, u1, i2, u2;
                inter_union(pr[1], pr[2], pr[3], pr[4],
                            tg_h[1], tg_h[2], tg_h[3], tg_h[4], i1, u1);
                inter_union(tg_h[6], tg_h[7], tg_h[8], tg_h[9],
                            tg_h[1], tg_h[2], tg_h[3], tg_h[4], i2, u2);

                bool r = (i1 * u2) > (i2 * u1);   // iou1 > iou2, division-free

                float px = r ? pr[1] : pr[6], py = r ? pr[2] : pr[7];
                float tx = r ? tg_h[1] : tg_h[6], ty = r ? tg_h[2] : tg_h[7];
                float pw = r ? pr[3] : pr[8], ph = r ? pr[4] : pr[9];
                float tw = r ? tg_h[3] : tg_h[8], th = r ? tg_h[4] : tg_h[9];

                float dx = px - tx, dy = py - ty;
                float cell_xy = dx * dx + dy * dy;
                float cell_wh = pw + tw - 2.0f * sqrt_approx(pw * tw)
                              + ph + th - 2.0f * sqrt_approx(ph * th);

                float num_r = r ? i1 : i2;
                float den_r = r ? u1 : u2;
                float iou_resp = (num_r > 0.0f) ? __fdividef(num_r, den_r) : 0.0f;

                float conf_resp  = r ? pr[0] : pr[5];
                float d_obj      = conf_resp - iou_resp;

                float conf_other = r ? pr[5] : pr[0];
                float noobj = obj_f * (conf_other * conf_other)
                            + (1.0f - obj_f) * (pr[0] * pr[0] + pr[5] * pr[5]);

                s_coord += obj_f * (cell_xy + cell_wh);
                s_obj   += obj_f * (d_obj * d_obj);
                s_noobj += noobj;
            }
        } else {
            // ---- CLASS thread: channels 10..29 of cell (cell0 + tid - CC) ----
            const int lt   = tid - CC;
            const int cell = cell0 + lt;
            if (cell < ncells) {
                const float2* cp = bp + (size_t)lt * 15 + 5;
                const float2* ct = bt + (size_t)lt * 15 + 5;
                float tg0 = bt[(size_t)lt * 15].x;   // target channel 0

                float cls = 0.0f;
#pragma unroll
                for (int i = 0; i < 10; i++) {
                    float2 v = cp[i];
                    float2 w = ct[i];
                    float d0 = v.x - w.x;
                    float d1 = v.y - w.y;
                    cls += d0 * d0 + d1 * d1;
                }
                float obj_f = (tg0 == 1.0f) ? 1.0f : 0.0f;
                s_class += obj_f * cls;
            }
        }
        __syncthreads();
    }

    // ---- intra-block reduction ----
    s_coord = warp_sum(s_coord);
    s_obj   = warp_sum(s_obj);
    s_noobj = warp_sum(s_noobj);
    s_class = warp_sum(s_class);

    __shared__ float sm[NT / 32][4];
    int lane = threadIdx.x & 31;
    int w    = threadIdx.x >> 5;
    if (lane == 0) {
        sm[w][0] = s_coord; sm[w][1] = s_obj;
        sm[w][2] = s_noobj; sm[w][3] = s_class;
    }
    __syncthreads();

    __shared__ bool is_last;
    if (threadIdx.x == 0) is_last = false;

    if (w == 0) {
        float a = (lane < NT / 32) ? sm[lane][0] : 0.0f;
        float bq = (lane < NT / 32) ? sm[lane][1] : 0.0f;
        float cq = (lane < NT / 32) ? sm[lane][2] : 0.0f;
        float dq = (lane < NT / 32) ? sm[lane][3] : 0.0f;
        a = warp_sum(a); bq = warp_sum(bq); cq = warp_sum(cq); dq = warp_sum(dq);
        if (lane == 0) {
            g_part[blockIdx.x][0] = a;
            g_part[blockIdx.x][1] = bq;
            g_part[blockIdx.x][2] = cq;
            g_part[blockIdx.x][3] = dq;
            __threadfence();
            unsigned int ticket = atomicAdd(&g_count, 1u);
            is_last = (ticket == gridDim.x - 1);
        }
    }
    __syncthreads();

    if (is_last) {
        const volatile float* gp = &g_part[0][0];
        double v0 = 0.0, v1 = 0.0, v2 = 0.0, v3 = 0.0;
        for (int i = threadIdx.x; i < (int)gridDim.x; i += NT) {
            v0 += (double)gp[4 * i + 0];
            v1 += (double)gp[4 * i + 1];
            v2 += (double)gp[4 * i + 2];
            v3 += (double)gp[4 * i + 3];
        }
        v0 = warp_sum_d(v0); v1 = warp_sum_d(v1);
        v2 = warp_sum_d(v2); v3 = warp_sum_d(v3);

        __shared__ double smd[NT / 32][4];
        if (lane == 0) { smd[w][0] = v0; smd[w][1] = v1; smd[w][2] = v2; smd[w][3] = v3; }
        __syncthreads();
        if (w == 0) {
            double a = (lane < NT / 32) ? smd[lane][0] : 0.0;
            double bq = (lane < NT / 32) ? smd[lane][1] : 0.0;
            double cq = (lane < NT / 32) ? smd[lane][2] : 0.0;
            double dq = (lane < NT / 32) ? smd[lane][3] : 0.0;
            a = warp_sum_d(a); bq = warp_sum_d(bq);
            cq = warp_sum_d(cq); dq = warp_sum_d(dq);
            if (lane == 0) {
                double coord = 5.0 * a;   // LAMBDA_COORD
                double objl  = bq;
                double noobj = 0.5 * cq;  // LAMBDA_NOOBJ
                double cls   = dq;
                out[0] = (float)(coord * (double)inv_bs);
                out[1] = (float)(objl  * (double)inv_bs);
                out[2] = (float)(noobj * (double)inv_bs);
                out[3] = (float)(cls   * (double)inv_bs);
                out[4] = (float)((coord + objl + noobj + cls) * (double)inv_bs);
                g_count = 0;
            }
        }
    }
}

extern "C" void kernel_launch(void* const* d_in, const int* in_sizes, int n_in,
                              void* d_out, int out_size) {
    const float* pred   = (const float*)d_in[0];
    const float* target = (const float*)d_in[1];
    float* out = (float*)d_out;

    int total   = in_sizes[0];                   // batch * 49 * 30
    int ncells  = total / CH;                    // batch * 49
    int batch   = ncells / CELLS_PB;
    int nchunks = (ncells + CC - 1) / CC;        // 3136 for batch=16384
    int nblocks = NSMS;
    if (nblocks > nchunks) nblocks = nchunks;
    if (nblocks > MAXBLOCKS) nblocks = MAXBLOCKS;
    float inv_bs = 1.0f / (float)batch;

    cudaFuncSetAttribute(yolo_pipe3_kernel,
                         cudaFuncAttributeMaxDynamicSharedMemorySize, SMEM_BYTES);
    yolo_pipe3_kernel<<<nblocks, NT, SMEM_BYTES>>>(pred, target, ncells, nchunks,
                                                   inv_bs, out);
}

// round 10
// speedup vs baseline: 1.3506x; 1.0502x over previous
#include <cuda_runtime.h>
#include <cstdint>

// YOLOv1 loss — TMA bulk-copy double-buffered streaming, 2 threads per cell.
// pred, target: float32 [batch*7*7*30]; out: 5 float32.

static constexpr int CH        = 30;
static constexpr int CELLS_PB  = 49;
static constexpr int NT        = 512;                 // threads per block
static constexpr int CC        = 256;                 // cells per chunk
static constexpr int STREAM_BYTES = CC * CH * 4;      // 30720 B per stream per chunk
static constexpr int BUF_BYTES = 2 * STREAM_BYTES;    // 61440 B per buffer (pred+tgt)
static constexpr int SMEM_BYTES = 2 * BUF_BYTES;      // 122880 B (double buffer)
static constexpr int NSMS      = 152;
static constexpr int MAXBLOCKS = 512;

__device__ float        g_part[MAXBLOCKS][4];
__device__ unsigned int g_count = 0;

// ---- TMA bulk + mbarrier helpers ----
__device__ __forceinline__ void bulk_copy(void* sdst, const void* gsrc,
                                          uint32_t bytes, uint32_t mbar) {
    uint32_t s = (uint32_t)__cvta_generic_to_shared(sdst);
    asm volatile(
        "cp.async.bulk.shared::cta.global.mbarrier::complete_tx::bytes "
        "[%0], [%1], %2, [%3];"
        :: "r"(s), "l"(gsrc), "r"(bytes), "r"(mbar) : "memory");
}
__device__ __forceinline__ void mbar_init(uint32_t mbar, uint32_t count) {
    asm volatile("mbarrier.init.shared.b64 [%0], %1;" :: "r"(mbar), "r"(count) : "memory");
}
__device__ __forceinline__ void mbar_expect_tx(uint32_t mbar, uint32_t tx) {
    asm volatile("mbarrier.arrive.expect_tx.shared.b64 _, [%0], %1;"
                 :: "r"(mbar), "r"(tx) : "memory");
}
__device__ __forceinline__ void mbar_wait(uint32_t mbar, uint32_t parity) {
    asm volatile(
        "{\n\t"
        ".reg .pred P1;\n\t"
        "WAIT_LOOP_%=:\n\t"
        "mbarrier.try_wait.parity.acquire.cta.shared::cta.b64 P1, [%0], %1, 0x989680;\n\t"
        "@P1 bra.uni WAIT_DONE_%=;\n\t"
        "bra.uni WAIT_LOOP_%=;\n\t"
        "WAIT_DONE_%=:\n\t"
        "}"
        :: "r"(mbar), "r"(parity) : "memory");
}

__device__ __forceinline__ float sqrt_approx(float x) {
    float r;
    asm("sqrt.approx.f32 %0, %1;" : "=f"(r) : "f"(x));
    return r;
}

__device__ __forceinline__ float warp_sum(float v) {
#pragma unroll
    for (int o = 16; o > 0; o >>= 1) v += __shfl_down_sync(0xffffffffu, v, o);
    return v;
}
__device__ __forceinline__ double warp_sum_d(double v) {
#pragma unroll
    for (int o = 16; o > 0; o >>= 1) v += __shfl_down_sync(0xffffffffu, v, o);
    return v;
}

__device__ __forceinline__ void inter_union(float x1, float y1, float w1, float h1,
                                            float x2, float y2, float w2, float h2,
                                            float& inter, float& uni) {
    float ml = fmaxf(x1 - w1 * 0.5f, x2 - w2 * 0.5f);
    float mr = fminf(x1 + w1 * 0.5f, x2 + w2 * 0.5f);
    float mt = fmaxf(y1 - h1 * 0.5f, y2 - h2 * 0.5f);
    float mb = fminf(y1 + h1 * 0.5f, y2 + h2 * 0.5f);
    float iw = fmaxf(mr - ml, 0.0f);
    float ih = fmaxf(mb - mt, 0.0f);
    inter = iw * ih;
    uni   = w1 * h1 + w2 * h2 - inter;
}

// Head-loss for one cell given pr[10], tg[10] (channels 0..9).
__device__ __forceinline__ void head_loss(const float pr[10], const float tg[10],
                                          float& s_coord, float& s_obj, float& s_noobj) {
    float obj_f = (tg[0] == 1.0f) ? 1.0f : 0.0f;

    float i1, u1, i2, u2;
    inter_union(pr[1], pr[2], pr[3], pr[4], tg[1], tg[2], tg[3], tg[4], i1, u1);
    inter_union(tg[6], tg[7], tg[8], tg[9], tg[1], tg[2], tg[3], tg[4], i2, u2);

    bool r = (i1 * u2) > (i2 * u1);   // iou1 > iou2, division-free

    float px = r ? pr[1] : pr[6], py = r ? pr[2] : pr[7];
    float tx = r ? tg[1] : tg[6], ty = r ? tg[2] : tg[7];
    float pw = r ? pr[3] : pr[8], ph = r ? pr[4] : pr[9];
    float tw = r ? tg[3] : tg[8], th = r ? tg[4] : tg[9];

    float dx = px - tx, dy = py - ty;
    float cell_xy = dx * dx + dy * dy;
    float cell_wh = pw + tw - 2.0f * sqrt_approx(pw * tw)
                  + ph + th - 2.0f * sqrt_approx(ph * th);

    float num_r = r ? i1 : i2;
    float den_r = r ? u1 : u2;
    float iou_resp = (num_r > 0.0f) ? __fdividef(num_r, den_r) : 0.0f;

    float conf_resp  = r ? pr[0] : pr[5];
    float d_obj      = conf_resp - iou_resp;

    float conf_other = r ? pr[5] : pr[0];
    float noobj = obj_f * (conf_other * conf_other)
                + (1.0f - obj_f) * (pr[0] * pr[0] + pr[5] * pr[5]);

    s_coord += obj_f * (cell_xy + cell_wh);
    s_obj   += obj_f * (d_obj * d_obj);
    s_noobj += noobj;
}

__global__ void __launch_bounds__(NT)
yolo_tma_kernel(const float* __restrict__ pred,
                const float* __restrict__ target,
                int ncells, int nfull, float inv_bs,
                float* __restrict__ out) {
    extern __shared__ float sbuf_f[];   // [2][BUF_BYTES/4]
    __shared__ uint64_t mbar_store[2];

    const int tid = threadIdx.x;
    const uint32_t mbar0 = (uint32_t)__cvta_generic_to_shared(&mbar_store[0]);
    const uint32_t mbar1 = mbar0 + 8;

    if (tid == 0) {
        mbar_init(mbar0, 1);
        mbar_init(mbar1, 1);
    }
    __syncthreads();

    // Contiguous balanced range of FULL chunks for this block.
    int nb   = gridDim.x;
    int base = nfull / nb;
    int rem  = nfull - base * nb;
    int b    = blockIdx.x;
    int c_begin = b * base + (b < rem ? b : rem);
    int c_end   = c_begin + base + (b < rem ? 1 : 0);

    auto stage = [&](int c, int which) {   // thread 0 only
        uint32_t mb = which ? mbar1 : mbar0;
        float* dst = sbuf_f + (size_t)which * (BUF_BYTES / 4);
        mbar_expect_tx(mb, BUF_BYTES);
        bulk_copy(dst, pred + (size_t)c * CC * CH, STREAM_BYTES, mb);
        bulk_copy(dst + STREAM_BYTES / 4, target + (size_t)c * CC * CH, STREAM_BYTES, mb);
    };

    float s_coord = 0.0f, s_obj = 0.0f, s_noobj = 0.0f, s_class = 0.0f;
    uint32_t phase[2] = {0u, 0u};

    if (c_begin < c_end && tid == 0) stage(c_begin, 0);

    for (int c = c_begin; c < c_end; c++) {
        int which = (c - c_begin) & 1;
        // Prefetch next chunk into the other buffer (its readers finished
        // at the __syncthreads ending iteration c-1).
        if (c + 1 < c_end && tid == 0) stage(c + 1, which ^ 1);

        mbar_wait(which ? mbar1 : mbar0, phase[which]);
        phase[which] ^= 1u;

        const float2* bp = reinterpret_cast<const float2*>(
            sbuf_f + (size_t)which * (BUF_BYTES / 4));
        const float2* bt = bp + STREAM_BYTES / 8;   // target region

        if (tid < CC) {
            // HEAD thread: channels 0..9 of cell tid
            const float2* cp = bp + (size_t)tid * 15;
            const float2* ct = bt + (size_t)tid * 15;
            float pr[10], tg_h[10];
#pragma unroll
            for (int i = 0; i < 5; i++) {
                float2 v = cp[i];
                pr[2 * i] = v.x; pr[2 * i + 1] = v.y;
                float2 w = ct[i];
                tg_h[2 * i] = w.x; tg_h[2 * i + 1] = w.y;
            }
            head_loss(pr, tg_h, s_coord, s_obj, s_noobj);
        } else {
            // CLASS thread: channels 10..29 of cell tid-CC
            const int lt = tid - CC;
            const float2* cp = bp + (size_t)lt * 15 + 5;
            const float2* ct = bt + (size_t)lt * 15 + 5;
            float tg0 = bt[(size_t)lt * 15].x;

            float cls = 0.0f;
#pragma unroll
            for (int i = 0; i < 10; i++) {
                float2 v = cp[i];
                float2 w = ct[i];
                float d0 = v.x - w.x;
                float d1 = v.y - w.y;
                cls += d0 * d0 + d1 * d1;
            }
            float obj_f = (tg0 == 1.0f) ? 1.0f : 0.0f;
            s_class += obj_f * cls;
        }
        __syncthreads();   // all readers done before buffer is re-staged
    }

    // ---- tail cells (ncells % CC), handled by last block from gmem ----
    int tail = ncells - nfull * CC;
    if (tail > 0 && blockIdx.x == gridDim.x - 1 && tid < tail) {
        const int cell = nfull * CC + tid;
        const float2* p2 = reinterpret_cast<const float2*>(pred   + (size_t)cell * CH);
        const float2* t2 = reinterpret_cast<const float2*>(target + (size_t)cell * CH);
        float pr[10], tg_h[10];
#pragma unroll
        for (int i = 0; i < 5; i++) {
            float2 v = __ldg(p2 + i);
            pr[2 * i] = v.x; pr[2 * i + 1] = v.y;
            float2 w = __ldg(t2 + i);
            tg_h[2 * i] = w.x; tg_h[2 * i + 1] = w.y;
        }
        float cls = 0.0f;
#pragma unroll
        for (int i = 5; i < 15; i++) {
            float2 v = __ldg(p2 + i);
            float2 w = __ldg(t2 + i);
            float d0 = v.x - w.x;
            float d1 = v.y - w.y;
            cls += d0 * d0 + d1 * d1;
        }
        head_loss(pr, tg_h, s_coord, s_obj, s_noobj);
        float obj_f = (tg_h[0] == 1.0f) ? 1.0f : 0.0f;
        s_class += obj_f * cls;
    }

    // ---- intra-block reduction ----
    s_coord = warp_sum(s_coord);
    s_obj   = warp_sum(s_obj);
    s_noobj = warp_sum(s_noobj);
    s_class = warp_sum(s_class);

    __shared__ float sm[NT / 32][4];
    int lane = threadIdx.x & 31;
    int w    = threadIdx.x >> 5;
    if (lane == 0) {
        sm[w][0] = s_coord; sm[w][1] = s_obj;
        sm[w][2] = s_noobj; sm[w][3] = s_class;
    }
    __syncthreads();

    __shared__ bool is_last;
    if (threadIdx.x == 0) is_last = false;

    if (w == 0) {
        float a = (lane < NT / 32) ? sm[lane][0] : 0.0f;
        float bq = (lane < NT / 32) ? sm[lane][1] : 0.0f;
        float cq = (lane < NT / 32) ? sm[lane][2] : 0.0f;
        float dq = (lane < NT / 32) ? sm[lane][3] : 0.0f;
        a = warp_sum(a); bq = warp_sum(bq); cq = warp_sum(cq); dq = warp_sum(dq);
        if (lane == 0) {
            g_part[blockIdx.x][0] = a;
            g_part[blockIdx.x][1] = bq;
            g_part[blockIdx.x][2] = cq;
            g_part[blockIdx.x][3] = dq;
            __threadfence();
            unsigned int ticket = atomicAdd(&g_count, 1u);
            is_last = (ticket == gridDim.x - 1);
        }
    }
    __syncthreads();

    // ---- last block folds partials (fp64, fixed order -> deterministic) ----
    if (is_last) {
        const volatile float* gp = &g_part[0][0];
        double v0 = 0.0, v1 = 0.0, v2 = 0.0, v3 = 0.0;
        for (int i = threadIdx.x; i < (int)gridDim.x; i += NT) {
            v0 += (double)gp[4 * i + 0];
            v1 += (double)gp[4 * i + 1];
            v2 += (double)gp[4 * i + 2];
            v3 += (double)gp[4 * i + 3];
        }
        v0 = warp_sum_d(v0); v1 = warp_sum_d(v1);
        v2 = warp_sum_d(v2); v3 = warp_sum_d(v3);

        __shared__ double smd[NT / 32][4];
        if (lane == 0) { smd[w][0] = v0; smd[w][1] = v1; smd[w][2] = v2; smd[w][3] = v3; }
        __syncthreads();
        if (w == 0) {
            double a = (lane < NT / 32) ? smd[lane][0] : 0.0;
            double bq = (lane < NT / 32) ? smd[lane][1] : 0.0;
            double cq = (lane < NT / 32) ? smd[lane][2] : 0.0;
            double dq = (lane < NT / 32) ? smd[lane][3] : 0.0;
            a = warp_sum_d(a); bq = warp_sum_d(bq);
            cq = warp_sum_d(cq); dq = warp_sum_d(dq);
            if (lane == 0) {
                double coord = 5.0 * a;   // LAMBDA_COORD
                double objl  = bq;
                double noobj = 0.5 * cq;  // LAMBDA_NOOBJ
                double cls   = dq;
                out[0] = (float)(coord * (double)inv_bs);
                out[1] = (float)(objl  * (double)inv_bs);
                out[2] = (float)(noobj * (double)inv_bs);
                out[3] = (float)(cls   * (double)inv_bs);
                out[4] = (float)((coord + objl + noobj + cls) * (double)inv_bs);
                g_count = 0;
            }
        }
    }
}

extern "C" void kernel_launch(void* const* d_in, const int* in_sizes, int n_in,
                              void* d_out, int out_size) {
    const float* pred   = (const float*)d_in[0];
    const float* target = (const float*)d_in[1];
    float* out = (float*)d_out;

    int total  = in_sizes[0];                    // batch * 49 * 30
    int ncells = total / CH;                     // batch * 49
    int batch  = ncells / CELLS_PB;
    int nfull  = ncells / CC;                    // 3136 for batch=16384
    int nblocks = NSMS;
    if (nblocks > nfull) nblocks = (nfull > 0) ? nfull : 1;
    if (nblocks > MAXBLOCKS) nblocks = MAXBLOCKS;
    float inv_bs = 1.0f / (float)batch;

    cudaFuncSetAttribute(yolo_tma_kernel,
                         cudaFuncAttributeMaxDynamicSharedMemorySize, SMEM_BYTES);
    yolo_tma_kernel<<<nblocks, NT, SMEM_BYTES>>>(pred, target, ncells, nfull,
                                                 inv_bs, out);
}